// round 12
// baseline (speedup 1.0000x reference)
#include <cuda_runtime.h>
#include <cuda_fp16.h>

// LightGCN layer, gather-form with direct fixed-capacity binning (no scan).
//   rows [0, n_items)            : h_item[d] = sum norm_ui * user_feat[ui_src]
//   rows [n_items, n_items+n_us) : h_user[d] = sum norm_iu * item_feat[iu_src]
// Output layout: [h_user (n_users*64) | h_item (n_items*64)]
// Combined half feature table: rows [0,n_users) = user, [n_users,+n_items) = item.
//
// Self-cleaning state: __device__ globals are zero-initialized at module load;
// k_gather resets each row's cursor after consuming it and k_overflow resets
// the overflow counter, so every call starts from zeroed state without a
// dedicated zeroing kernel. Deterministic: same inputs -> same work -> same
// output on every call.
//
// Edges are binned into per-destination-row slot arrays of capacity CAP.
// Overflow (probability ~1e-12 for Poisson degree distributions, but handled
// for correctness on any input) goes to a global list applied by a final
// atomic kernel (cold path).

#define MAX_ROWS  150002
#define CAP       96
#define OVF_CAP   65536
#define D         64

// 16-byte vector of 4 half2 (8 halves) -> single LDG.128 / STG.128.
struct __align__(16) H2x4 { __half2 a, b, c, d; };

__device__ int  g_cursor [MAX_ROWS + 2];
__device__ int  g_ovf_count;
__device__ int4 g_ovf    [OVF_CAP];              // (row, src, w_bits, pad)
__device__ int2 g_slots  [(size_t)MAX_ROWS * CAP];
__device__ H2x4 g_feat_h [MAX_ROWS * D / 8];     // 8 halves per entry

// ------------------------------------------- fused convert + direct binning
__device__ __forceinline__ void bin_edge(int d, int s, float w) {
    int pos = atomicAdd(&g_cursor[d], 1);
    if (pos < CAP) {
        g_slots[(size_t)d * CAP + pos] = make_int2(s, __float_as_int(w));
    } else {
        int o = atomicAdd(&g_ovf_count, 1);
        if (o < OVF_CAP) g_ovf[o] = make_int4(d, s, __float_as_int(w), 0);
    }
}

__global__ void k_bin(const float4* __restrict__ user,
                      const float4* __restrict__ item,
                      int n8u, int n8total,
                      const int*   __restrict__ ui_src,
                      const int*   __restrict__ ui_dst,
                      const float* __restrict__ norm_ui,
                      const int*   __restrict__ iu_src,
                      const int*   __restrict__ iu_dst,
                      const float* __restrict__ norm_iu,
                      int E_ui, int E_iu, int n_items, int n_users) {
    int i = blockIdx.x * blockDim.x + threadIdx.x;

    // ---- convert part (fp32 -> fp16 table, 8 floats -> one H2x4)
    if (i < n8total) {
        const float4* src = (i < n8u) ? (user + 2 * (size_t)i)
                                      : (item + 2 * (size_t)(i - n8u));
        float4 a = src[0];
        float4 b = src[1];
        H2x4 o;
        o.a = __floats2half2_rn(a.x, a.y);
        o.b = __floats2half2_rn(a.z, a.w);
        o.c = __floats2half2_rn(b.x, b.y);
        o.d = __floats2half2_rn(b.z, b.w);
        g_feat_h[i] = o;
    }

    // ---- binning part (4 edges per thread via int4/float4)
    int nq_ui = E_ui >> 2;
    int nq_iu = E_iu >> 2;
    if (i < nq_ui) {
        int4   s4 = ((const int4*)ui_src)[i];
        int4   d4 = ((const int4*)ui_dst)[i];
        float4 w4 = ((const float4*)norm_ui)[i];
        bin_edge(d4.x, s4.x, w4.x);
        bin_edge(d4.y, s4.y, w4.y);
        bin_edge(d4.z, s4.z, w4.z);
        bin_edge(d4.w, s4.w, w4.w);
    } else if (i < nq_ui + nq_iu) {
        int q = i - nq_ui;
        int4   s4 = ((const int4*)iu_src)[q];
        int4   d4 = ((const int4*)iu_dst)[q];
        float4 w4 = ((const float4*)norm_iu)[q];
        bin_edge(n_items + d4.x, n_users + s4.x, w4.x);
        bin_edge(n_items + d4.y, n_users + s4.y, w4.y);
        bin_edge(n_items + d4.z, n_users + s4.z, w4.z);
        bin_edge(n_items + d4.w, n_users + s4.w, w4.w);
    } else {
        int t = i - (nq_ui + nq_iu);
        int tail_ui = E_ui & 3;
        int tail_iu = E_iu & 3;
        if (t < tail_ui) {
            int e = (nq_ui << 2) + t;
            bin_edge(ui_dst[e], ui_src[e], norm_ui[e]);
        } else if (t < tail_ui + tail_iu) {
            int e = (nq_iu << 2) + (t - tail_ui);
            bin_edge(n_items + iu_dst[e], n_users + iu_src[e], norm_iu[e]);
        }
    }
}

// ------------------------------------------- gather: one warp per output row
// 4 edges per step; each 8-lane group loads its own slot entry directly.
// Lane 0 resets the row cursor after reading (self-cleaning for next call).
__global__ void __launch_bounds__(256)
k_gather(float* __restrict__ out, int n_items, int n_users) {
    int gid = blockIdx.x * blockDim.x + threadIdx.x;
    int row = gid >> 5;
    int n_total = n_items + n_users;
    if (row >= n_total) return;

    int lane  = threadIdx.x & 31;
    int group = lane >> 3;       // which of 4 edges per step
    int c     = lane & 7;        // 16B chunk within the 128B half row

    float* orow;
    if (row < n_items) {
        orow = out + ((size_t)(n_users + row) << 6);   // h_item
    } else {
        orow = out + ((size_t)(row - n_items) << 6);   // h_user
    }

    int cnt = __ldg(&g_cursor[row]);
    if (lane == 0) g_cursor[row] = 0;            // reset for next call
    if (cnt > CAP) cnt = CAP;                    // overflow handled later
    const int2* slots = g_slots + (size_t)row * CAP;

    float acc[8];
    #pragma unroll
    for (int k = 0; k < 8; k++) acc[k] = 0.f;

    #pragma unroll 4
    for (int e0 = 0; e0 < cnt; e0 += 4) {
        int e = e0 + group;
        int2 ent = (e < cnt) ? __ldg(&slots[e]) : make_int2(0, 0);
        float w = __int_as_float(ent.y);         // 0 for padded -> no-op
        H2x4 hv = g_feat_h[(size_t)ent.x * 8 + c];
        float2 f0 = __half22float2(hv.a);
        float2 f1 = __half22float2(hv.b);
        float2 f2 = __half22float2(hv.c);
        float2 f3 = __half22float2(hv.d);
        acc[0] += f0.x * w;  acc[1] += f0.y * w;
        acc[2] += f1.x * w;  acc[3] += f1.y * w;
        acc[4] += f2.x * w;  acc[5] += f2.y * w;
        acc[6] += f3.x * w;  acc[7] += f3.y * w;
    }

    // reduce 4 groups -> lanes 0-7
    #pragma unroll
    for (int k = 0; k < 8; k++) {
        acc[k] += __shfl_xor_sync(0xffffffffu, acc[k], 8);
        acc[k] += __shfl_xor_sync(0xffffffffu, acc[k], 16);
    }

    if (lane < 8) {
        float4* p = (float4*)(orow + (c << 3));
        p[0] = make_float4(acc[0], acc[1], acc[2], acc[3]);
        p[1] = make_float4(acc[4], acc[5], acc[6], acc[7]);
    }
}

// ------------------------------------------- overflow fixup (cold path)
// Also resets g_ovf_count for the next call (self-cleaning).
__global__ void k_overflow(float* __restrict__ out, int n_items, int n_users) {
    int n = g_ovf_count;
    if (n > OVF_CAP) n = OVF_CAP;
    if (n > 0) {
        const __half* ft = (const __half*)g_feat_h;
        for (int idx = threadIdx.x; idx < n * D; idx += blockDim.x) {
            int e = idx >> 6;
            int f = idx & 63;
            int4 ent = g_ovf[e];
            int row = ent.x;
            float w = __int_as_float(ent.z);
            float v = __half2float(ft[(size_t)ent.y * D + f]);
            float* orow = (row < n_items)
                        ? out + ((size_t)(n_users + row) << 6)
                        : out + ((size_t)(row - n_items) << 6);
            atomicAdd(&orow[f], v * w);
        }
        __syncthreads();
        if (threadIdx.x == 0) g_ovf_count = 0;
    }
}

// ---------------------------------------------------------------- launch
extern "C" void kernel_launch(void* const* d_in, const int* in_sizes, int n_in,
                              void* d_out, int out_size) {
    const float* user_feat = (const float*)d_in[0];
    const float* item_feat = (const float*)d_in[1];
    const float* norm_ui   = (const float*)d_in[2];
    const float* norm_iu   = (const float*)d_in[3];
    const int*   ui_src    = (const int*)d_in[4];
    const int*   ui_dst    = (const int*)d_in[5];
    const int*   iu_src    = (const int*)d_in[6];
    const int*   iu_dst    = (const int*)d_in[7];

    float* out = (float*)d_out;

    int n_users = in_sizes[0] / D;
    int n_items = in_sizes[1] / D;
    int E_ui    = in_sizes[4];
    int E_iu    = in_sizes[6];
    int n_total = n_items + n_users;

    int n8u      = n_users * D / 8;
    int n8total  = n8u + n_items * D / 8;
    int nq_total = (E_ui >> 2) + (E_iu >> 2) + (E_ui & 3) + (E_iu & 3);

    // 1. fused convert + direct binning (single pass over edges).
    //    Cursors/overflow counter are zero: zero-initialized at module load,
    //    then reset by k_gather / k_overflow on every call.
    {
        int work = (n8total > nq_total) ? n8total : nq_total;
        k_bin<<<(work + 255) / 256, 256>>>((const float4*)user_feat,
                                           (const float4*)item_feat,
                                           n8u, n8total,
                                           ui_src, ui_dst, norm_ui,
                                           iu_src, iu_dst, norm_iu,
                                           E_ui, E_iu, n_items, n_users);
    }

    // 2. gather: one warp per output row (resets cursors)
    long long threads = (long long)n_total * 32;
    k_gather<<<(int)((threads + 255) / 256), 256>>>(out, n_items, n_users);

    // 3. overflow fixup (no-op unless a row exceeded CAP; resets counter)
    k_overflow<<<1, 256>>>(out, n_items, n_users);
}

// round 13
// speedup vs baseline: 2.8016x; 2.8016x over previous
#include <cuda_runtime.h>
#include <cuda_fp16.h>

// LightGCN layer, gather-form with direct fixed-capacity binning (no scan).
//   rows [0, n_items)            : h_item[d] = sum norm_ui * user_feat[ui_src]
//   rows [n_items, n_items+n_us) : h_user[d] = sum norm_iu * item_feat[iu_src]
// Output layout: [h_user (n_users*64) | h_item (n_items*64)]
// Combined half feature table: rows [0,n_users) = user, [n_users,+n_items) = item.
//
// Edges are binned into per-destination-row slot arrays of capacity CAP.
// CAP=72 keeps the slots array (86MB) + feat table (19MB) inside the 126MB L2.
// Overflow (P(Poisson(40)>72) ~ 1e-6 per row, but handled for correctness on
// any input) goes to a global list applied by a final atomic kernel.

#define MAX_ROWS  150002
#define CAP       72
#define OVF_CAP   65536
#define D         64

// 16-byte vector of 4 half2 (8 halves) -> single LDG.128 / STG.128.
struct __align__(16) H2x4 { __half2 a, b, c, d; };

__device__ int  g_cursor [MAX_ROWS + 2];         // padded to /4 for int4 zero
__device__ int  g_ovf_count;
__device__ int4 g_ovf    [OVF_CAP];              // (row, src, w_bits, pad)
__device__ int2 g_slots  [(size_t)MAX_ROWS * CAP];
__device__ H2x4 g_feat_h [MAX_ROWS * D / 8];     // 8 halves per entry

// ---------------------------------------------------------------- zero (int4)
__global__ void k_zero(int n4) {
    int i = blockIdx.x * blockDim.x + threadIdx.x;
    if (i < n4) ((int4*)g_cursor)[i] = make_int4(0, 0, 0, 0);
    if (i == 0) g_ovf_count = 0;
}

// ------------------------------------------- fused convert + direct binning
__device__ __forceinline__ void bin_edge(int d, int s, float w) {
    int pos = atomicAdd(&g_cursor[d], 1);
    if (pos < CAP) {
        g_slots[(size_t)d * CAP + pos] = make_int2(s, __float_as_int(w));
    } else {
        int o = atomicAdd(&g_ovf_count, 1);
        if (o < OVF_CAP) g_ovf[o] = make_int4(d, s, __float_as_int(w), 0);
    }
}

__global__ void k_bin(const float4* __restrict__ user,
                      const float4* __restrict__ item,
                      int n8u, int n8total,
                      const int*   __restrict__ ui_src,
                      const int*   __restrict__ ui_dst,
                      const float* __restrict__ norm_ui,
                      const int*   __restrict__ iu_src,
                      const int*   __restrict__ iu_dst,
                      const float* __restrict__ norm_iu,
                      int E_ui, int E_iu, int n_items, int n_users) {
    int i = blockIdx.x * blockDim.x + threadIdx.x;

    // ---- convert part (fp32 -> fp16 table, 8 floats -> one H2x4)
    if (i < n8total) {
        const float4* src = (i < n8u) ? (user + 2 * (size_t)i)
                                      : (item + 2 * (size_t)(i - n8u));
        float4 a = src[0];
        float4 b = src[1];
        H2x4 o;
        o.a = __floats2half2_rn(a.x, a.y);
        o.b = __floats2half2_rn(a.z, a.w);
        o.c = __floats2half2_rn(b.x, b.y);
        o.d = __floats2half2_rn(b.z, b.w);
        g_feat_h[i] = o;
    }

    // ---- binning part (4 edges per thread via int4/float4)
    int nq_ui = E_ui >> 2;
    int nq_iu = E_iu >> 2;
    if (i < nq_ui) {
        int4   s4 = ((const int4*)ui_src)[i];
        int4   d4 = ((const int4*)ui_dst)[i];
        float4 w4 = ((const float4*)norm_ui)[i];
        bin_edge(d4.x, s4.x, w4.x);
        bin_edge(d4.y, s4.y, w4.y);
        bin_edge(d4.z, s4.z, w4.z);
        bin_edge(d4.w, s4.w, w4.w);
    } else if (i < nq_ui + nq_iu) {
        int q = i - nq_ui;
        int4   s4 = ((const int4*)iu_src)[q];
        int4   d4 = ((const int4*)iu_dst)[q];
        float4 w4 = ((const float4*)norm_iu)[q];
        bin_edge(n_items + d4.x, n_users + s4.x, w4.x);
        bin_edge(n_items + d4.y, n_users + s4.y, w4.y);
        bin_edge(n_items + d4.z, n_users + s4.z, w4.z);
        bin_edge(n_items + d4.w, n_users + s4.w, w4.w);
    } else {
        int t = i - (nq_ui + nq_iu);
        int tail_ui = E_ui & 3;
        int tail_iu = E_iu & 3;
        if (t < tail_ui) {
            int e = (nq_ui << 2) + t;
            bin_edge(ui_dst[e], ui_src[e], norm_ui[e]);
        } else if (t < tail_ui + tail_iu) {
            int e = (nq_iu << 2) + (t - tail_ui);
            bin_edge(n_items + iu_dst[e], n_users + iu_src[e], norm_iu[e]);
        }
    }
}

// ------------------------------------------- gather: one warp per output row
// 4 edges per step; each 8-lane group loads its own slot entry directly.
// NOTE: no stores to g_cursor here — mixing a store into this kernel's
// read-only path caused a 2.3x regression (R12).
__global__ void __launch_bounds__(256)
k_gather(float* __restrict__ out, int n_items, int n_users) {
    int gid = blockIdx.x * blockDim.x + threadIdx.x;
    int row = gid >> 5;
    int n_total = n_items + n_users;
    if (row >= n_total) return;

    int lane  = threadIdx.x & 31;
    int group = lane >> 3;       // which of 4 edges per step
    int c     = lane & 7;        // 16B chunk within the 128B half row

    float* orow;
    if (row < n_items) {
        orow = out + ((size_t)(n_users + row) << 6);   // h_item
    } else {
        orow = out + ((size_t)(row - n_items) << 6);   // h_user
    }

    int cnt = __ldg(&g_cursor[row]);
    if (cnt > CAP) cnt = CAP;                    // overflow handled later
    const int2* slots = g_slots + (size_t)row * CAP;

    float acc[8];
    #pragma unroll
    for (int k = 0; k < 8; k++) acc[k] = 0.f;

    #pragma unroll 4
    for (int e0 = 0; e0 < cnt; e0 += 4) {
        int e = e0 + group;
        int2 ent = (e < cnt) ? __ldg(&slots[e]) : make_int2(0, 0);
        float w = __int_as_float(ent.y);         // 0 for padded -> no-op
        H2x4 hv = g_feat_h[(size_t)ent.x * 8 + c];
        float2 f0 = __half22float2(hv.a);
        float2 f1 = __half22float2(hv.b);
        float2 f2 = __half22float2(hv.c);
        float2 f3 = __half22float2(hv.d);
        acc[0] += f0.x * w;  acc[1] += f0.y * w;
        acc[2] += f1.x * w;  acc[3] += f1.y * w;
        acc[4] += f2.x * w;  acc[5] += f2.y * w;
        acc[6] += f3.x * w;  acc[7] += f3.y * w;
    }

    // reduce 4 groups -> lanes 0-7
    #pragma unroll
    for (int k = 0; k < 8; k++) {
        acc[k] += __shfl_xor_sync(0xffffffffu, acc[k], 8);
        acc[k] += __shfl_xor_sync(0xffffffffu, acc[k], 16);
    }

    if (lane < 8) {
        float4* p = (float4*)(orow + (c << 3));
        p[0] = make_float4(acc[0], acc[1], acc[2], acc[3]);
        p[1] = make_float4(acc[4], acc[5], acc[6], acc[7]);
    }
}

// ------------------------------------------- overflow fixup (cold path)
__global__ void k_overflow(float* __restrict__ out, int n_items, int n_users) {
    int n = g_ovf_count;
    if (n > OVF_CAP) n = OVF_CAP;
    if (n == 0) return;
    const __half* ft = (const __half*)g_feat_h;
    for (int idx = threadIdx.x; idx < n * D; idx += blockDim.x) {
        int e = idx >> 6;
        int f = idx & 63;
        int4 ent = g_ovf[e];
        int row = ent.x;
        float w = __int_as_float(ent.z);
        float v = __half2float(ft[(size_t)ent.y * D + f]);
        float* orow = (row < n_items)
                    ? out + ((size_t)(n_users + row) << 6)
                    : out + ((size_t)(row - n_items) << 6);
        atomicAdd(&orow[f], v * w);
    }
}

// ---------------------------------------------------------------- launch
extern "C" void kernel_launch(void* const* d_in, const int* in_sizes, int n_in,
                              void* d_out, int out_size) {
    const float* user_feat = (const float*)d_in[0];
    const float* item_feat = (const float*)d_in[1];
    const float* norm_ui   = (const float*)d_in[2];
    const float* norm_iu   = (const float*)d_in[3];
    const int*   ui_src    = (const int*)d_in[4];
    const int*   ui_dst    = (const int*)d_in[5];
    const int*   iu_src    = (const int*)d_in[6];
    const int*   iu_dst    = (const int*)d_in[7];

    float* out = (float*)d_out;

    int n_users = in_sizes[0] / D;
    int n_items = in_sizes[1] / D;
    int E_ui    = in_sizes[4];
    int E_iu    = in_sizes[6];
    int n_total = n_items + n_users;

    int n8u      = n_users * D / 8;
    int n8total  = n8u + n_items * D / 8;
    int nq_total = (E_ui >> 2) + (E_iu >> 2) + (E_ui & 3) + (E_iu & 3);

    // 1. zero cursors + overflow counter (int4 vectorized)
    int n4 = (n_total + 3) / 4;
    k_zero<<<(n4 + 255) / 256, 256>>>(n4);

    // 2. fused convert + direct binning (single pass over edges)
    {
        int work = (n8total > nq_total) ? n8total : nq_total;
        k_bin<<<(work + 255) / 256, 256>>>((const float4*)user_feat,
                                           (const float4*)item_feat,
                                           n8u, n8total,
                                           ui_src, ui_dst, norm_ui,
                                           iu_src, iu_dst, norm_iu,
                                           E_ui, E_iu, n_items, n_users);
    }

    // 3. gather: one warp per output row
    long long threads = (long long)n_total * 32;
    k_gather<<<(int)((threads + 255) / 256), 256>>>(out, n_items, n_users);

    // 4. overflow fixup (no-op unless a row exceeded CAP)
    k_overflow<<<1, 256>>>(out, n_items, n_users);
}

// round 14
// speedup vs baseline: 2.8923x; 1.0324x over previous
#include <cuda_runtime.h>
#include <cuda_fp16.h>

// LightGCN layer, gather-form with direct fixed-capacity binning (no scan),
// split into two independent relation chains overlapped on two streams:
//   chain 1 (default stream): convert user feats + bin ui edges -> gather items
//   chain 2 (side stream)   : convert item feats + bin iu edges -> gather users
// Chains touch disjoint cursor rows, slot rows, feat-table halves and output
// halves, so they are fully independent; fork/join via events inside capture.
//
// Output layout: [h_user (n_users*64) | h_item (n_items*64)]
// Combined half feature table: rows [0,n_users) = user, [n_users,+n_items) = item.
// Row space: [0, n_items) = item destinations, [n_items, n_total) = user dests.

#define MAX_ROWS  150002
#define CAP       72
#define OVF_CAP   65536
#define D         64

// 16-byte vector of 4 half2 (8 halves) -> single LDG.128 / STG.128.
struct __align__(16) H2x4 { __half2 a, b, c, d; };

__device__ int  g_cursor [MAX_ROWS + 2];         // padded to /4 for int4 zero
__device__ int  g_ovf_count;
__device__ int4 g_ovf    [OVF_CAP];              // (row, src, w_bits, pad)
__device__ int2 g_slots  [(size_t)MAX_ROWS * CAP];
__device__ H2x4 g_feat_h [MAX_ROWS * D / 8];     // 8 halves per entry

// ---------------------------------------------------------------- zero (int4)
__global__ void k_zero(int n4) {
    int i = blockIdx.x * blockDim.x + threadIdx.x;
    if (i < n4) ((int4*)g_cursor)[i] = make_int4(0, 0, 0, 0);
    if (i == 0) g_ovf_count = 0;
}

// ------------------------------------------- fused convert + direct binning
// One relation per launch: converts its feat half and bins its edges.
__device__ __forceinline__ void bin_edge(int d, int s, float w) {
    int pos = atomicAdd(&g_cursor[d], 1);
    if (pos < CAP) {
        g_slots[(size_t)d * CAP + pos] = make_int2(s, __float_as_int(w));
    } else {
        int o = atomicAdd(&g_ovf_count, 1);
        if (o < OVF_CAP) g_ovf[o] = make_int4(d, s, __float_as_int(w), 0);
    }
}

__global__ void k_bin(const float4* __restrict__ feat,
                      int n8, int feat_off,
                      const int*   __restrict__ src,
                      const int*   __restrict__ dst,
                      const float* __restrict__ norm,
                      int E, int dst_off, int src_off) {
    int i = blockIdx.x * blockDim.x + threadIdx.x;

    // ---- convert part (fp32 -> fp16 table, 8 floats -> one H2x4)
    if (i < n8) {
        const float4* p = feat + 2 * (size_t)i;
        float4 a = p[0];
        float4 b = p[1];
        H2x4 o;
        o.a = __floats2half2_rn(a.x, a.y);
        o.b = __floats2half2_rn(a.z, a.w);
        o.c = __floats2half2_rn(b.x, b.y);
        o.d = __floats2half2_rn(b.z, b.w);
        g_feat_h[feat_off + i] = o;
    }

    // ---- binning part (4 edges per thread via int4/float4)
    int nq = E >> 2;
    if (i < nq) {
        int4   s4 = ((const int4*)src)[i];
        int4   d4 = ((const int4*)dst)[i];
        float4 w4 = ((const float4*)norm)[i];
        bin_edge(dst_off + d4.x, src_off + s4.x, w4.x);
        bin_edge(dst_off + d4.y, src_off + s4.y, w4.y);
        bin_edge(dst_off + d4.z, src_off + s4.z, w4.z);
        bin_edge(dst_off + d4.w, src_off + s4.w, w4.w);
    } else {
        int t = i - nq;
        int tail = E & 3;
        if (t < tail) {
            int e = (nq << 2) + t;
            bin_edge(dst_off + dst[e], src_off + src[e], norm[e]);
        }
    }
}

// ------------------------------------------- gather: one warp per output row
// 4 edges per step; each 8-lane group loads its own slot entry directly.
// Row range [row_begin, row_end) per launch. Body identical to the 131.3us
// baseline (no stores to read-only state -- R12 lesson).
__global__ void __launch_bounds__(256)
k_gather(float* __restrict__ out, int row_begin, int row_end,
         int n_items, int n_users) {
    int gid = blockIdx.x * blockDim.x + threadIdx.x;
    int row = row_begin + (gid >> 5);
    if (row >= row_end) return;

    int lane  = threadIdx.x & 31;
    int group = lane >> 3;       // which of 4 edges per step
    int c     = lane & 7;        // 16B chunk within the 128B half row

    float* orow;
    if (row < n_items) {
        orow = out + ((size_t)(n_users + row) << 6);   // h_item
    } else {
        orow = out + ((size_t)(row - n_items) << 6);   // h_user
    }

    int cnt = __ldg(&g_cursor[row]);
    if (cnt > CAP) cnt = CAP;                    // overflow handled later
    const int2* slots = g_slots + (size_t)row * CAP;

    float acc[8];
    #pragma unroll
    for (int k = 0; k < 8; k++) acc[k] = 0.f;

    #pragma unroll 4
    for (int e0 = 0; e0 < cnt; e0 += 4) {
        int e = e0 + group;
        int2 ent = (e < cnt) ? __ldg(&slots[e]) : make_int2(0, 0);
        float w = __int_as_float(ent.y);         // 0 for padded -> no-op
        H2x4 hv = g_feat_h[(size_t)ent.x * 8 + c];
        float2 f0 = __half22float2(hv.a);
        float2 f1 = __half22float2(hv.b);
        float2 f2 = __half22float2(hv.c);
        float2 f3 = __half22float2(hv.d);
        acc[0] += f0.x * w;  acc[1] += f0.y * w;
        acc[2] += f1.x * w;  acc[3] += f1.y * w;
        acc[4] += f2.x * w;  acc[5] += f2.y * w;
        acc[6] += f3.x * w;  acc[7] += f3.y * w;
    }

    // reduce 4 groups -> lanes 0-7
    #pragma unroll
    for (int k = 0; k < 8; k++) {
        acc[k] += __shfl_xor_sync(0xffffffffu, acc[k], 8);
        acc[k] += __shfl_xor_sync(0xffffffffu, acc[k], 16);
    }

    if (lane < 8) {
        float4* p = (float4*)(orow + (c << 3));
        p[0] = make_float4(acc[0], acc[1], acc[2], acc[3]);
        p[1] = make_float4(acc[4], acc[5], acc[6], acc[7]);
    }
}

// ------------------------------------------- overflow fixup (cold path)
__global__ void k_overflow(float* __restrict__ out, int n_items, int n_users) {
    int n = g_ovf_count;
    if (n > OVF_CAP) n = OVF_CAP;
    if (n == 0) return;
    const __half* ft = (const __half*)g_feat_h;
    for (int idx = threadIdx.x; idx < n * D; idx += blockDim.x) {
        int e = idx >> 6;
        int f = idx & 63;
        int4 ent = g_ovf[e];
        int row = ent.x;
        float w = __int_as_float(ent.z);
        float v = __half2float(ft[(size_t)ent.y * D + f]);
        float* orow = (row < n_items)
                    ? out + ((size_t)(n_users + row) << 6)
                    : out + ((size_t)(row - n_items) << 6);
        atomicAdd(&orow[f], v * w);
    }
}

// ---------------------------------------------------------------- launch
extern "C" void kernel_launch(void* const* d_in, const int* in_sizes, int n_in,
                              void* d_out, int out_size) {
    const float* user_feat = (const float*)d_in[0];
    const float* item_feat = (const float*)d_in[1];
    const float* norm_ui   = (const float*)d_in[2];
    const float* norm_iu   = (const float*)d_in[3];
    const int*   ui_src    = (const int*)d_in[4];
    const int*   ui_dst    = (const int*)d_in[5];
    const int*   iu_src    = (const int*)d_in[6];
    const int*   iu_dst    = (const int*)d_in[7];

    float* out = (float*)d_out;

    int n_users = in_sizes[0] / D;
    int n_items = in_sizes[1] / D;
    int E_ui    = in_sizes[4];
    int E_iu    = in_sizes[6];
    int n_total = n_items + n_users;

    int n8u = n_users * D / 8;
    int n8i = n_items * D / 8;

    // One-time side stream + fork/join events (host objects only; per-call
    // submitted work is identical on every call).
    static cudaStream_t s2 = nullptr;
    static cudaEvent_t evFork = nullptr, evJoin = nullptr;
    if (s2 == nullptr) {
        cudaStreamCreateWithFlags(&s2, cudaStreamNonBlocking);
        cudaEventCreateWithFlags(&evFork, cudaEventDisableTiming);
        cudaEventCreateWithFlags(&evJoin, cudaEventDisableTiming);
    }

    // 1. zero cursors + overflow counter (default stream)
    int n4 = (n_total + 3) / 4;
    k_zero<<<(n4 + 255) / 256, 256>>>(n4);

    // Fork: side stream depends on k_zero.
    cudaEventRecord(evFork, 0);
    cudaStreamWaitEvent(s2, evFork, 0);

    // 2a. chain 1 (default): convert user feats + bin ui edges -> gather items
    {
        int nq = (E_ui >> 2) + (E_ui & 3);
        int work = (n8u > nq) ? n8u : nq;
        k_bin<<<(work + 255) / 256, 256>>>((const float4*)user_feat, n8u, 0,
                                           ui_src, ui_dst, norm_ui,
                                           E_ui, /*dst_off=*/0, /*src_off=*/0);
        long long th = (long long)n_items * 32;
        k_gather<<<(int)((th + 255) / 256), 256>>>(out, 0, n_items,
                                                   n_items, n_users);
    }

    // 2b. chain 2 (s2): convert item feats + bin iu edges -> gather users
    {
        int nq = (E_iu >> 2) + (E_iu & 3);
        int work = (n8i > nq) ? n8i : nq;
        k_bin<<<(work + 255) / 256, 256, 0, s2>>>((const float4*)item_feat,
                                                  n8i, n8u,
                                                  iu_src, iu_dst, norm_iu,
                                                  E_iu, /*dst_off=*/n_items,
                                                  /*src_off=*/n_users);
        long long th = (long long)n_users * 32;
        k_gather<<<(int)((th + 255) / 256), 256, 0, s2>>>(out, n_items, n_total,
                                                          n_items, n_users);
    }

    // Join: default stream waits for chain 2.
    cudaEventRecord(evJoin, s2);
    cudaStreamWaitEvent(0, evJoin, 0);

    // 3. overflow fixup (no-op unless a row exceeded CAP)
    k_overflow<<<1, 256>>>(out, n_items, n_users);
}